// round 3
// baseline (speedup 1.0000x reference)
#include <cuda_runtime.h>
#include <math.h>
#include <stdint.h>

// ---------------------------------------------------------------------------
// 2-layer LSTM, T=512, B=64, H=512, fp32. Persistent kernel, 128 CTAs x 256.
// CTA j owns hidden cols [4j,4j+4) (16 gate rows/layer); weights resident in
// smem transposed [k][16c]. Per layer-step: 8 warp-teams K-split the GEMM,
// thread tile = 4 gate rows x 8 batches, packed fma.rn.f32x2, cp.async.cg
// double-buffered 16-k A tiles, __syncwarp-only staging sync. h buffers in
// 3-slot rotation => ONE grid barrier per timestep. c state in registers.
// ---------------------------------------------------------------------------

#define T_LEN 512
#define BSZ   64
#define HID   512
#define NCTA  128
#define NTHR  256

// smem layout (floats)
#define WT_STRIDE   (512*16)                 // one weight mat [512][16]
#define AB_OFF      (4*WT_STRIDE)            // 32768
#define TILE_FLOATS (16*64)                  // one A tile [16 k][64 b]
#define AB_TEAM     (2*TILE_FLOATS)          // double buffer per team
#define GB_OFF      (AB_OFF + 8*AB_TEAM)     // 49152
#define GB_CSTRIDE  68
#define GB_TEAM     (16*GB_CSTRIDE)          // 1088
#define BS_OFF      (GB_OFF + 8*GB_TEAM)     // 57856
#define SMEM_FLOATS (BS_OFF + 32)            // 57888
#define SMEM_BYTES  (SMEM_FLOATS*4)          // 231552 (< 232448 cap)

// persistent scratch ([k][b] layouts)
__device__ float g_xT [T_LEN][HID][BSZ];     // x transposed per step
__device__ float g_h0T[3][HID][BSZ];         // 3-slot rotation
__device__ float g_h1T[3][HID][BSZ];
__device__ unsigned g_cnt;                   // returns to 0 after each barrier
__device__ unsigned g_gen;                   // monotonic across launches (ok)

__device__ __forceinline__ float sigm(float x) { return 1.0f / (1.0f + expf(-x)); }

__device__ __forceinline__ unsigned long long pack2(float x) {
    unsigned long long d;
    asm("mov.b64 %0, {%1, %1};" : "=l"(d) : "f"(x));
    return d;
}
__device__ __forceinline__ unsigned long long ffma2(
    unsigned long long a, unsigned long long b, unsigned long long c) {
    unsigned long long d;
    asm("fma.rn.f32x2 %0, %1, %2, %3;" : "=l"(d) : "l"(a), "l"(b), "l"(c));
    return d;
}
__device__ __forceinline__ void cp16(float* dst, const float* src) {
    unsigned s = (unsigned)__cvta_generic_to_shared(dst);
    asm volatile("cp.async.cg.shared.global [%0], [%1], 16;" :: "r"(s), "l"(src));
}

// Grid-wide barrier (proven). All 128 CTAs co-resident.
__device__ __forceinline__ void grid_bar() {
    __threadfence();
    __syncthreads();
    if (threadIdx.x == 0) {
        volatile unsigned* vg = &g_gen;
        unsigned g = *vg;
        unsigned t = atomicAdd(&g_cnt, 1u);
        if (t == NCTA - 1) {
            atomicExch(&g_cnt, 0u);
            __threadfence();
            atomicAdd(&g_gen, 1u);
        } else {
            while (*vg == g) { }
        }
        __threadfence();
    }
    __syncthreads();
}

// Team kt (one warp) computes partial gates for k in [kt*64,(kt+1)*64) of
// A0 . Wx^T and A1 . Wh^T. A0/A1 are [512][64] in gmem. Thread tile:
// 4 gate rows (cq*4..+3) x 8 batches (bq*8..+7). acc[ci][bp] = f32x2 pairs.
__device__ __forceinline__ void gemm_layer(
    float* sm, int wbase, const float* __restrict__ A0,
    const float* __restrict__ A1,
    int kt, int lane, int cq, int bq, unsigned long long acc[4][4])
{
    float* Ab = sm + AB_OFF + kt * AB_TEAM;
    const int toff = lane * 4;     // float offset for linear 16B staging

    #pragma unroll
    for (int ci = 0; ci < 4; ci++)
        acc[ci][0] = acc[ci][1] = acc[ci][2] = acc[ci][3] = 0ull;

    // prefetch tiles 0,1 (both from A0)
    #pragma unroll
    for (int pi = 0; pi < 2; pi++) {
        const float* src = A0 + (kt * 64 + pi * 16) * 64;
        float* dst = Ab + pi * TILE_FLOATS;
        #pragma unroll
        for (int j = 0; j < 8; j++)
            cp16(dst + toff + j * 128, src + toff + j * 128);
        asm volatile("cp.async.commit_group;" ::: "memory");
    }

    #pragma unroll 1
    for (int i = 0; i < 8; i++) {
        if (i == 7) asm volatile("cp.async.wait_group 0;" ::: "memory");
        else        asm volatile("cp.async.wait_group 1;" ::: "memory");
        __syncwarp();   // all lanes' groups landed -> whole tile valid

        {
            const float* wp = sm + (wbase + (i >> 2)) * WT_STRIDE
                            + (kt * 64 + (i & 3) * 16) * 16 + cq * 4;
            const float* ap = Ab + (i & 1) * TILE_FLOATS + bq * 8;
            #pragma unroll
            for (int kk = 0; kk < 16; kk++) {
                float4 w = *reinterpret_cast<const float4*>(wp + kk * 16);
                ulonglong2 av0 = *reinterpret_cast<const ulonglong2*>(ap + kk * 64);
                ulonglong2 av1 = *reinterpret_cast<const ulonglong2*>(ap + kk * 64 + 4);
                unsigned long long w0 = pack2(w.x), w1 = pack2(w.y),
                                   w2 = pack2(w.z), w3 = pack2(w.w);
                acc[0][0] = ffma2(av0.x, w0, acc[0][0]);
                acc[0][1] = ffma2(av0.y, w0, acc[0][1]);
                acc[0][2] = ffma2(av1.x, w0, acc[0][2]);
                acc[0][3] = ffma2(av1.y, w0, acc[0][3]);
                acc[1][0] = ffma2(av0.x, w1, acc[1][0]);
                acc[1][1] = ffma2(av0.y, w1, acc[1][1]);
                acc[1][2] = ffma2(av1.x, w1, acc[1][2]);
                acc[1][3] = ffma2(av1.y, w1, acc[1][3]);
                acc[2][0] = ffma2(av0.x, w2, acc[2][0]);
                acc[2][1] = ffma2(av0.y, w2, acc[2][1]);
                acc[2][2] = ffma2(av1.x, w2, acc[2][2]);
                acc[2][3] = ffma2(av1.y, w2, acc[2][3]);
                acc[3][0] = ffma2(av0.x, w3, acc[3][0]);
                acc[3][1] = ffma2(av0.y, w3, acc[3][1]);
                acc[3][2] = ffma2(av1.x, w3, acc[3][2]);
                acc[3][3] = ffma2(av1.y, w3, acc[3][3]);
            }
        }
        __syncwarp();   // all lanes done reading before overwrite
        if (i < 6) {
            int ni = i + 2;
            const float* Asel = (ni < 4) ? A0 : A1;
            const float* src = Asel + (kt * 64 + (ni & 3) * 16) * 64;
            float* dst = Ab + (i & 1) * TILE_FLOATS;   // ni&1 == i&1
            #pragma unroll
            for (int j = 0; j < 8; j++)
                cp16(dst + toff + j * 128, src + toff + j * 128);
            asm volatile("cp.async.commit_group;" ::: "memory");
        }
    }
}

__device__ __forceinline__ void store_partials(
    float* sm, int kt, int cq, int bq, unsigned long long acc[4][4])
{
    float* gb = sm + GB_OFF + kt * GB_TEAM + (cq * 4) * GB_CSTRIDE + bq * 8;
    #pragma unroll
    for (int ci = 0; ci < 4; ci++) {
        float* p = gb + ci * GB_CSTRIDE;
        *reinterpret_cast<unsigned long long*>(p    ) = acc[ci][0];
        *reinterpret_cast<unsigned long long*>(p + 2) = acc[ci][1];
        *reinterpret_cast<unsigned long long*>(p + 4) = acc[ci][2];
        *reinterpret_cast<unsigned long long*>(p + 6) = acc[ci][3];
    }
}

__global__ void transpose_x(const float* __restrict__ x) {
    __shared__ float tile[32][33];
    int t  = blockIdx.z;
    int k0 = blockIdx.x << 5, b0 = blockIdx.y << 5;
    const float* src = x + ((size_t)t * BSZ + b0) * HID + k0;
    #pragma unroll
    for (int i = threadIdx.y; i < 32; i += 8)
        tile[i][threadIdx.x] = src[(size_t)i * HID + threadIdx.x];
    __syncthreads();
    #pragma unroll
    for (int i = threadIdx.y; i < 32; i += 8)
        g_xT[t][k0 + i][b0 + threadIdx.x] = tile[threadIdx.x][i];
}

__global__ void __launch_bounds__(NTHR, 1) lstm_persistent(
    const float* __restrict__ Wxh,  // [2, 2048, 512]
    const float* __restrict__ Whh,  // [2, 2048, 512]
    const float* __restrict__ bxh,  // [2, 2048]
    const float* __restrict__ bhh,  // [2, 2048]
    float* __restrict__ out)        // [T*B*H] ++ hT[2,B,H] ++ cT[2,B,H]
{
    extern __shared__ float sm[];
    const int tid = threadIdx.x;
    const int bj  = blockIdx.x;

    // ---- prologue: weights -> smem transposed [k][16c]; biases; zero h ----
    for (int idx4 = tid; idx4 < 8192; idx4 += NTHR) {   // float4 units
        int m = idx4 >> 11, rem = idx4 & 2047;
        int c = rem >> 7, k4 = (rem & 127) << 2;
        int layer = m >> 1;
        const float* base = (m & 1) ? Whh : Wxh;
        const float* src = base + ((size_t)layer * 2048
                         + (size_t)(c >> 2) * 512 + (bj << 2) + (c & 3)) * 512 + k4;
        float4 v = *reinterpret_cast<const float4*>(src);
        float* d = sm + m * WT_STRIDE + k4 * 16 + c;
        d[0] = v.x; d[16] = v.y; d[32] = v.z; d[48] = v.w;
    }
    if (tid < 32) {
        int l = tid >> 4, j = tid & 15;
        int n = (j >> 2) * 512 + (bj << 2) + (j & 3);
        sm[BS_OFF + tid] = bxh[l * 2048 + n] + bhh[l * 2048 + n];
    }
    {   // zero slot 2 (read at t=0)
        int i = bj * NTHR + tid;              // [0, 32768)
        (&g_h0T[2][0][0])[i] = 0.f;
        (&g_h1T[2][0][0])[i] = 0.f;
    }
    grid_bar();

    const int kt  = tid >> 5, lane = tid & 31;   // gemm role (team = warp)
    const int cq  = lane >> 3, bq = lane & 7;    // 4 gate rows x 8 batches
    const int ub  = tid >> 2, ucc = tid & 3;     // update role
    const int col = (bj << 2) + ucc;
    const float* bs = sm + BS_OFF;
    float c0r = 0.f, c1r = 0.f, h0last = 0.f, h1last = 0.f;

    unsigned long long acc[4][4];
    int rp = 2, wp = 0;

    for (int t = 0; t < T_LEN; t++) {
        // ================= layer 0 =================
        gemm_layer(sm, 0, &g_xT[t][0][0], &g_h0T[rp][0][0], kt, lane, cq, bq, acc);
        __syncthreads();                    // prev update reads done
        store_partials(sm, kt, cq, bq, acc);
        __syncthreads();
        {
            float gate[4];
            #pragma unroll
            for (int g = 0; g < 4; g++) {
                const float* q = sm + GB_OFF + (g * 4 + ucc) * GB_CSTRIDE + ub;
                float s = bs[g * 4 + ucc];
                #pragma unroll
                for (int k2 = 0; k2 < 8; k2++) s += q[k2 * GB_TEAM];
                gate[g] = s;
            }
            float ig = sigm(gate[0]), fg = sigm(gate[1]);
            float gg = tanhf(gate[2]), og = sigm(gate[3]);
            c0r = fg * c0r + ig * gg;
            h0last = og * tanhf(c0r);
            g_h0T[wp][col][ub] = h0last;
        }
        grid_bar();                         // the ONE barrier per step

        // ================= layer 1 =================
        gemm_layer(sm, 2, &g_h0T[wp][0][0], &g_h1T[rp][0][0], kt, lane, cq, bq, acc);
        __syncthreads();
        store_partials(sm, kt, cq, bq, acc);
        __syncthreads();
        {
            float gate[4];
            #pragma unroll
            for (int g = 0; g < 4; g++) {
                const float* q = sm + GB_OFF + (g * 4 + ucc) * GB_CSTRIDE + ub;
                float s = bs[16 + g * 4 + ucc];
                #pragma unroll
                for (int k2 = 0; k2 < 8; k2++) s += q[k2 * GB_TEAM];
                gate[g] = s;
            }
            float ig = sigm(gate[0]), fg = sigm(gate[1]);
            float gg = tanhf(gate[2]), og = sigm(gate[3]);
            c1r = fg * c1r + ig * gg;
            h1last = og * tanhf(c1r);
            g_h1T[wp][col][ub] = h1last;
            out[(size_t)t * (BSZ * HID) + ub * HID + col] = h1last;
        }
        // no grid barrier here: 3-slot rotation makes next-step L0 reads safe
        rp = wp;
        wp = (wp == 2) ? 0 : wp + 1;
    }

    // ---- epilogue: (hT, cT) straight from registers ----
    {
        const size_t OFF = (size_t)T_LEN * BSZ * HID;
        int li = ub * HID + col;
        out[OFF +          li] = h0last;
        out[OFF +  32768 + li] = h1last;
        out[OFF +  65536 + li] = c0r;
        out[OFF +  98304 + li] = c1r;
    }
}

extern "C" void kernel_launch(void* const* d_in, const int* in_sizes, int n_in,
                              void* d_out, int out_size) {
    const float* x   = (const float*)d_in[0];
    const float* Wxh = (const float*)d_in[1];
    const float* Whh = (const float*)d_in[2];
    const float* bxh = (const float*)d_in[3];
    const float* bhh = (const float*)d_in[4];
    float* out = (float*)d_out;

    transpose_x<<<dim3(16, 2, T_LEN), dim3(32, 8)>>>(x);

    cudaFuncSetAttribute(lstm_persistent,
                         cudaFuncAttributeMaxDynamicSharedMemorySize, SMEM_BYTES);
    lstm_persistent<<<NCTA, NTHR, SMEM_BYTES>>>(Wxh, Whh, bxh, bhh, out);
}

// round 5
// speedup vs baseline: 1.2773x; 1.2773x over previous
#include <cuda_runtime.h>
#include <math.h>
#include <stdint.h>

// ---------------------------------------------------------------------------
// 2-layer LSTM, T=512, B=64, H=512, fp32. Persistent kernel, 128 CTAs x 512
// threads (16 warps/SM, 4/SMSP -- occupancy is the round-4 lever).
// CTA j owns hidden cols [4j,4j+4) (16 gate rows/layer); weights resident in
// smem transposed [k][16c]. 8 teams of 2 warps K-split the GEMM (named
// barriers), thread tile 4 gate rows x 4 batches, packed fma.rn.f32x2,
// cp.async.cg double-buffered 16-k A tiles. h buffers in 3-slot rotation =>
// one grid barrier per timestep. Cell state in registers.
// ---------------------------------------------------------------------------

#define T_LEN 512
#define BSZ   64
#define HID   512
#define NCTA  128
#define NTHR  512

// smem layout (floats)
#define WT_STRIDE   (512*16)                 // one weight mat [512][16]
#define AB_OFF      (4*WT_STRIDE)            // 32768
#define TILE_FLOATS (16*64)                  // one A tile [16 k][64 b]
#define AB_TEAM     (2*TILE_FLOATS)          // 2048: double buffer per team
#define GB_OFF      (AB_OFF + 8*AB_TEAM)     // 49152
#define GB_CSTRIDE  68
#define GB_TEAM     (16*GB_CSTRIDE)          // 1088
#define BS_OFF      (GB_OFF + 8*GB_TEAM)     // 57856
#define SMEM_FLOATS (BS_OFF + 32)            // 57888
#define SMEM_BYTES  (SMEM_FLOATS*4)          // 231552 B

// persistent scratch ([k][b] layouts)
__device__ float g_xT [T_LEN][HID][BSZ];     // x transposed per step
__device__ float g_h0T[3][HID][BSZ];         // 3-slot rotation
__device__ float g_h1T[3][HID][BSZ];
__device__ unsigned g_cnt;                   // returns to 0 after each barrier
__device__ unsigned g_gen;                   // monotonic across launches (ok)

__device__ __forceinline__ float sigm(float x) { return 1.0f / (1.0f + expf(-x)); }

__device__ __forceinline__ unsigned long long pack2(float x) {
    unsigned long long d;
    asm("mov.b64 %0, {%1, %1};" : "=l"(d) : "f"(x));
    return d;
}
__device__ __forceinline__ unsigned long long ffma2(
    unsigned long long a, unsigned long long b, unsigned long long c) {
    unsigned long long d;
    asm("fma.rn.f32x2 %0, %1, %2, %3;" : "=l"(d) : "l"(a), "l"(b), "l"(c));
    return d;
}
__device__ __forceinline__ void cp16(float* dst, const float* src) {
    unsigned s = (unsigned)__cvta_generic_to_shared(dst);
    asm volatile("cp.async.cg.shared.global [%0], [%1], 16;" :: "r"(s), "l"(src));
}

// Grid-wide barrier (proven). All 128 CTAs co-resident (1 CTA/SM).
__device__ __forceinline__ void grid_bar() {
    __threadfence();
    __syncthreads();
    if (threadIdx.x == 0) {
        volatile unsigned* vg = &g_gen;
        unsigned g = *vg;
        unsigned t = atomicAdd(&g_cnt, 1u);
        if (t == NCTA - 1) {
            atomicExch(&g_cnt, 0u);
            __threadfence();
            atomicAdd(&g_gen, 1u);
        } else {
            while (*vg == g) { }
        }
        __threadfence();
    }
    __syncthreads();
}

// Team kt (2 warps, 64 threads, named barrier kt+1) computes partial gates
// for k in [kt*64,(kt+1)*64) of A0 . Wx^T and A1 . Wh^T. A0/A1: [512][64]
// in gmem. Thread tile: 4 gate rows (cq*4..+3) x 4 batches (bq*4..+3).
__device__ __forceinline__ void gemm_layer(
    float* sm, int wbase, const float* __restrict__ A0,
    const float* __restrict__ A1,
    int kt, int t64, int cq, int bq, unsigned long long acc[4][2])
{
    float* Ab = sm + AB_OFF + kt * AB_TEAM;
    const int toff = t64 * 4;   // 64 threads x 16B per staging pass

    #pragma unroll
    for (int ci = 0; ci < 4; ci++)
        acc[ci][0] = acc[ci][1] = 0ull;

    // prefetch sub-tiles 0,1 (both from A0)
    #pragma unroll
    for (int pi = 0; pi < 2; pi++) {
        const float* src = A0 + (kt * 64 + pi * 16) * 64;
        float* dst = Ab + pi * TILE_FLOATS;
        #pragma unroll
        for (int j = 0; j < 4; j++)
            cp16(dst + toff + j * 256, src + toff + j * 256);
        asm volatile("cp.async.commit_group;" ::: "memory");
    }

    #pragma unroll 1
    for (int i = 0; i < 8; i++) {
        if (i == 7) asm volatile("cp.async.wait_group 0;" ::: "memory");
        else        asm volatile("cp.async.wait_group 1;" ::: "memory");
        asm volatile("bar.sync %0, 64;" :: "r"(kt + 1) : "memory");  // tile valid

        {
            const float* wp = sm + (wbase + (i >> 2)) * WT_STRIDE
                            + (kt * 64 + (i & 3) * 16) * 16 + cq * 4;
            const float* ap = Ab + (i & 1) * TILE_FLOATS + bq * 4;
            #pragma unroll
            for (int kk = 0; kk < 16; kk++) {
                float4 w = *reinterpret_cast<const float4*>(wp + kk * 16);
                ulonglong2 av = *reinterpret_cast<const ulonglong2*>(ap + kk * 64);
                unsigned long long w0 = pack2(w.x), w1 = pack2(w.y),
                                   w2 = pack2(w.z), w3 = pack2(w.w);
                acc[0][0] = ffma2(av.x, w0, acc[0][0]);
                acc[0][1] = ffma2(av.y, w0, acc[0][1]);
                acc[1][0] = ffma2(av.x, w1, acc[1][0]);
                acc[1][1] = ffma2(av.y, w1, acc[1][1]);
                acc[2][0] = ffma2(av.x, w2, acc[2][0]);
                acc[2][1] = ffma2(av.y, w2, acc[2][1]);
                acc[3][0] = ffma2(av.x, w3, acc[3][0]);
                acc[3][1] = ffma2(av.y, w3, acc[3][1]);
            }
        }
        asm volatile("bar.sync %0, 64;" :: "r"(kt + 1) : "memory");  // reads done
        if (i < 6) {
            int ni = i + 2;
            const float* Asel = (ni < 4) ? A0 : A1;
            const float* src = Asel + (kt * 64 + (ni & 3) * 16) * 64;
            float* dst = Ab + (i & 1) * TILE_FLOATS;    // ni&1 == i&1
            #pragma unroll
            for (int j = 0; j < 4; j++)
                cp16(dst + toff + j * 256, src + toff + j * 256);
            asm volatile("cp.async.commit_group;" ::: "memory");
        }
    }
}

__device__ __forceinline__ void store_partials(
    float* sm, int kt, int cq, int bq, unsigned long long acc[4][2])
{
    float* gb = sm + GB_OFF + kt * GB_TEAM + (cq * 4) * GB_CSTRIDE + bq * 4;
    #pragma unroll
    for (int ci = 0; ci < 4; ci++) {
        float* p = gb + ci * GB_CSTRIDE;
        *reinterpret_cast<unsigned long long*>(p    ) = acc[ci][0];
        *reinterpret_cast<unsigned long long*>(p + 2) = acc[ci][1];
    }
}

__global__ void transpose_x(const float* __restrict__ x) {
    __shared__ float tile[32][33];
    int t  = blockIdx.z;
    int k0 = blockIdx.x << 5, b0 = blockIdx.y << 5;
    const float* src = x + ((size_t)t * BSZ + b0) * HID + k0;
    #pragma unroll
    for (int i = threadIdx.y; i < 32; i += 8)
        tile[i][threadIdx.x] = src[(size_t)i * HID + threadIdx.x];
    __syncthreads();
    #pragma unroll
    for (int i = threadIdx.y; i < 32; i += 8)
        g_xT[t][k0 + i][b0 + threadIdx.x] = tile[threadIdx.x][i];
}

__global__ void __launch_bounds__(NTHR, 1) lstm_persistent(
    const float* __restrict__ Wxh,  // [2, 2048, 512]
    const float* __restrict__ Whh,  // [2, 2048, 512]
    const float* __restrict__ bxh,  // [2, 2048]
    const float* __restrict__ bhh,  // [2, 2048]
    float* __restrict__ out)        // [T*B*H] ++ hT[2,B,H] ++ cT[2,B,H]
{
    extern __shared__ float sm[];
    const int tid = threadIdx.x;
    const int bj  = blockIdx.x;

    // ---- prologue: weights -> smem transposed [k][16c]; biases; zero h ----
    for (int idx4 = tid; idx4 < 8192; idx4 += NTHR) {   // float4 units
        int m = idx4 >> 11, rem = idx4 & 2047;
        int c = rem >> 7, k4 = (rem & 127) << 2;
        int layer = m >> 1;
        const float* base = (m & 1) ? Whh : Wxh;
        const float* src = base + ((size_t)layer * 2048
                         + (size_t)(c >> 2) * 512 + (bj << 2) + (c & 3)) * 512 + k4;
        float4 v = *reinterpret_cast<const float4*>(src);
        float* d = sm + m * WT_STRIDE + k4 * 16 + c;
        d[0] = v.x; d[16] = v.y; d[32] = v.z; d[48] = v.w;
    }
    if (tid < 32) {
        int l = tid >> 4, j = tid & 15;
        int n = (j >> 2) * 512 + (bj << 2) + (j & 3);
        sm[BS_OFF + tid] = bxh[l * 2048 + n] + bhh[l * 2048 + n];
    }
    if (tid < 256) {   // zero slot 2 (read at t=0); 128*256 = 32768 exactly
        int i = bj * 256 + tid;
        (&g_h0T[2][0][0])[i] = 0.f;
        (&g_h1T[2][0][0])[i] = 0.f;
    }
    grid_bar();

    const int kt  = tid >> 6, t64 = tid & 63;    // team (2 warps) role
    const int cq  = t64 >> 4, bq = t64 & 15;     // 4 gate rows x 4 batches
    const int ub  = (tid & 255) >> 2, ucc = tid & 3;  // update role (tid<256)
    const int col = (bj << 2) + ucc;
    const float* bs = sm + BS_OFF;
    float c0r = 0.f, c1r = 0.f, h0last = 0.f, h1last = 0.f;

    unsigned long long acc[4][2];
    int rp = 2, wp = 0;

    for (int t = 0; t < T_LEN; t++) {
        // ================= layer 0 =================
        gemm_layer(sm, 0, &g_xT[t][0][0], &g_h0T[rp][0][0], kt, t64, cq, bq, acc);
        __syncthreads();                    // prev update reads of gbuf done
        store_partials(sm, kt, cq, bq, acc);
        __syncthreads();
        if (tid < 256) {
            float gate[4];
            #pragma unroll
            for (int g = 0; g < 4; g++) {
                const float* q = sm + GB_OFF + (g * 4 + ucc) * GB_CSTRIDE + ub;
                float s = bs[g * 4 + ucc];
                #pragma unroll
                for (int k2 = 0; k2 < 8; k2++) s += q[k2 * GB_TEAM];
                gate[g] = s;
            }
            float ig = sigm(gate[0]), fg = sigm(gate[1]);
            float gg = tanhf(gate[2]), og = sigm(gate[3]);
            c0r = fg * c0r + ig * gg;
            h0last = og * tanhf(c0r);
            g_h0T[wp][col][ub] = h0last;
        }
        grid_bar();                         // the one barrier per step

        // ================= layer 1 =================
        gemm_layer(sm, 2, &g_h0T[wp][0][0], &g_h1T[rp][0][0], kt, t64, cq, bq, acc);
        __syncthreads();
        store_partials(sm, kt, cq, bq, acc);
        __syncthreads();
        if (tid < 256) {
            float gate[4];
            #pragma unroll
            for (int g = 0; g < 4; g++) {
                const float* q = sm + GB_OFF + (g * 4 + ucc) * GB_CSTRIDE + ub;
                float s = bs[16 + g * 4 + ucc];
                #pragma unroll
                for (int k2 = 0; k2 < 8; k2++) s += q[k2 * GB_TEAM];
                gate[g] = s;
            }
            float ig = sigm(gate[0]), fg = sigm(gate[1]);
            float gg = tanhf(gate[2]), og = sigm(gate[3]);
            c1r = fg * c1r + ig * gg;
            h1last = og * tanhf(c1r);
            g_h1T[wp][col][ub] = h1last;
            out[(size_t)t * (BSZ * HID) + ub * HID + col] = h1last;
        }
        // no grid barrier: 3-slot rotation makes next-step L0 reads safe
        rp = wp;
        wp = (wp == 2) ? 0 : wp + 1;
    }

    // ---- epilogue: (hT, cT) straight from registers ----
    if (tid < 256) {
        const size_t OFF = (size_t)T_LEN * BSZ * HID;
        int li = ub * HID + col;
        out[OFF +          li] = h0last;
        out[OFF +  32768 + li] = h1last;
        out[OFF +  65536 + li] = c0r;
        out[OFF +  98304 + li] = c1r;
    }
}

extern "C" void kernel_launch(void* const* d_in, const int* in_sizes, int n_in,
                              void* d_out, int out_size) {
    const float* x   = (const float*)d_in[0];
    const float* Wxh = (const float*)d_in[1];
    const float* Whh = (const float*)d_in[2];
    const float* bxh = (const float*)d_in[3];
    const float* bhh = (const float*)d_in[4];
    float* out = (float*)d_out;

    transpose_x<<<dim3(16, 2, T_LEN), dim3(32, 8)>>>(x);

    cudaFuncSetAttribute(lstm_persistent,
                         cudaFuncAttributeMaxDynamicSharedMemorySize, SMEM_BYTES);
    lstm_persistent<<<NCTA, NTHR, SMEM_BYTES>>>(Wxh, Whh, bxh, bhh, out);
}